// round 2
// baseline (speedup 1.0000x reference)
#include <cuda_runtime.h>
#include <math.h>

// Problem constants
#define NTOT  32768
#define DIM   256
#define NB    16
#define VIS   512
#define MSK   1536
#define NV    (NB*VIS)   // 8192
#define NM    (NB*MSK)   // 24576
#define HID   128
#define NHEAD 8
#define DH    32

// ---------------- scratch (device globals; no allocation allowed) -------------
__device__ float g_gbuf[NTOT*DIM];   // gelu(ln(coord-mlp1)) per point
__device__ float g_X[NTOT*DIM];     // kv rows (vis) / q rows (msk), point order
__device__ float g_Q[NM*DIM];
__device__ float g_K[NV*DIM];
__device__ float g_V[NV*DIM];
__device__ float g_O[NM*DIM];       // attention output (pre-wo)
__device__ float g_AO[NM*DIM];      // after wo
__device__ float g_MF[NM*DIM];      // masked features (post residual LN)
__device__ float g_w1T[DIM*HID];    // d_w1 transposed [k][n]
__device__ float g_w2T[HID*HID];    // d_w2 transposed [k][n]
__device__ int   g_mm[6];           // ordered-int min(0..2) / max(3..5) of coords

// ---------------- helpers ----------------------------------------------------
__device__ __forceinline__ int f2ord(float f){ int i=__float_as_int(f); return i>=0 ? i : (i^0x7fffffff); }
__device__ __forceinline__ float ord2f(int i){ return __int_as_float(i>=0 ? i : (i^0x7fffffff)); }
__device__ __forceinline__ float gelu(float x){ return 0.5f*x*(1.0f+erff(x*0.70710678118654752f)); }

__global__ void init_mm_kernel(){
    int t=threadIdx.x;
    if(t<3) g_mm[t]=0x7fffffff;
    else if(t<6) g_mm[t]=0x80000000;
}

__global__ void mm_kernel(const float* __restrict__ coord){
    float mn0=1e30f,mn1=1e30f,mn2=1e30f,mx0=-1e30f,mx1=-1e30f,mx2=-1e30f;
    for(int p=blockIdx.x*blockDim.x+threadIdx.x; p<NTOT; p+=gridDim.x*blockDim.x){
        float a=coord[p*3+0], b=coord[p*3+1], c=coord[p*3+2];
        mn0=fminf(mn0,a); mx0=fmaxf(mx0,a);
        mn1=fminf(mn1,b); mx1=fmaxf(mx1,b);
        mn2=fminf(mn2,c); mx2=fmaxf(mx2,c);
    }
    for(int o=16;o;o>>=1){
        mn0=fminf(mn0,__shfl_xor_sync(0xffffffffu,mn0,o));
        mn1=fminf(mn1,__shfl_xor_sync(0xffffffffu,mn1,o));
        mn2=fminf(mn2,__shfl_xor_sync(0xffffffffu,mn2,o));
        mx0=fmaxf(mx0,__shfl_xor_sync(0xffffffffu,mx0,o));
        mx1=fmaxf(mx1,__shfl_xor_sync(0xffffffffu,mx1,o));
        mx2=fmaxf(mx2,__shfl_xor_sync(0xffffffffu,mx2,o));
    }
    if((threadIdx.x&31)==0){
        atomicMin(&g_mm[0],f2ord(mn0)); atomicMin(&g_mm[1],f2ord(mn1)); atomicMin(&g_mm[2],f2ord(mn2));
        atomicMax(&g_mm[3],f2ord(mx0)); atomicMax(&g_mm[4],f2ord(mx1)); atomicMax(&g_mm[5],f2ord(mx2));
    }
}

// ----- pos-embed stage 1: h = gelu(LN(cn @ pe_w1^T + pe_b1))  (warp per point)
__global__ void pe_stage1_kernel(const float* __restrict__ coord,
                                 const float* __restrict__ w1, const float* __restrict__ b1,
                                 const float* __restrict__ gam, const float* __restrict__ bet){
    int w=threadIdx.x>>5, lane=threadIdx.x&31;
    int p=blockIdx.x*8+w;
    float lo0=ord2f(g_mm[0]), lo1=ord2f(g_mm[1]), lo2=ord2f(g_mm[2]);
    float s0=fmaxf(ord2f(g_mm[3])-lo0,1.0f);
    float s1=fmaxf(ord2f(g_mm[4])-lo1,1.0f);
    float s2=fmaxf(ord2f(g_mm[5])-lo2,1.0f);
    float c0=(coord[p*3+0]-lo0)/s0;
    float c1=(coord[p*3+1]-lo1)/s1;
    float c2=(coord[p*3+2]-lo2)/s2;
    float v[8]; float s=0.f, ss=0.f;
#pragma unroll
    for(int j=0;j<8;j++){
        int d=lane+32*j;
        float h=c0*w1[d*3+0]+c1*w1[d*3+1]+c2*w1[d*3+2]+b1[d];
        v[j]=h; s+=h; ss+=h*h;
    }
    for(int o=16;o;o>>=1){ s+=__shfl_xor_sync(0xffffffffu,s,o); ss+=__shfl_xor_sync(0xffffffffu,ss,o); }
    float mean=s*(1.0f/256.0f);
    float rstd=rsqrtf(ss*(1.0f/256.0f)-mean*mean+1e-5f);
#pragma unroll
    for(int j=0;j<8;j++){
        int d=lane+32*j;
        float t=(v[j]-mean)*rstd*gam[d]+bet[d];
        g_gbuf[p*DIM+d]=gelu(t);
    }
}

// ----- generic 256-K GEMM: C[m,n] = sum_k A[map(m),k]*W[n,k] + bias[n] (+epi)
// gatherMode: 0 direct, 1 masked->point, 2 visible->point
// epiMode:    0 plain, 1 combine (add encoded row for vis / mask_token for msk)
__global__ void gemm256_kernel(const float* __restrict__ A, const float* __restrict__ W,
                               const float* __restrict__ bias, float* __restrict__ C,
                               int gatherMode, int epiMode,
                               const float* __restrict__ encoded, const float* __restrict__ mtok){
    __shared__ float As[16][64];
    __shared__ float Ws[16][64];
    const int t=threadIdx.x;
    const int m0=blockIdx.x*64, n0=blockIdx.y*64;
    const int lr=t>>2, kq=t&3;
    int cm=m0+lr;
    int arow;
    if(gatherMode==1)      arow=(cm/1536)*2048+512+(cm%1536);
    else if(gatherMode==2) arow=(cm>>9)*2048+(cm&511);
    else                   arow=cm;
    const float* aptr=A+(size_t)arow*DIM+kq*4;
    const float* wptr=W+(size_t)(n0+lr)*DIM+kq*4;
    const int tx=t&15, ty=t>>4;
    float acc[4][4];
#pragma unroll
    for(int i=0;i<4;i++)
#pragma unroll
        for(int j=0;j<4;j++) acc[i][j]=0.f;

    for(int kt=0;kt<16;kt++){
        float4 av=*(const float4*)(aptr+kt*16);
        float4 wv=*(const float4*)(wptr+kt*16);
        __syncthreads();
        As[kq*4+0][lr]=av.x; As[kq*4+1][lr]=av.y; As[kq*4+2][lr]=av.z; As[kq*4+3][lr]=av.w;
        Ws[kq*4+0][lr]=wv.x; Ws[kq*4+1][lr]=wv.y; Ws[kq*4+2][lr]=wv.z; Ws[kq*4+3][lr]=wv.w;
        __syncthreads();
#pragma unroll
        for(int kk=0;kk<16;kk++){
            float4 a=*(const float4*)&As[kk][ty*4];
            float4 b=*(const float4*)&Ws[kk][tx*4];
            acc[0][0]+=a.x*b.x; acc[0][1]+=a.x*b.y; acc[0][2]+=a.x*b.z; acc[0][3]+=a.x*b.w;
            acc[1][0]+=a.y*b.x; acc[1][1]+=a.y*b.y; acc[1][2]+=a.y*b.z; acc[1][3]+=a.y*b.w;
            acc[2][0]+=a.z*b.x; acc[2][1]+=a.z*b.y; acc[2][2]+=a.z*b.z; acc[2][3]+=a.z*b.w;
            acc[3][0]+=a.w*b.x; acc[3][1]+=a.w*b.y; acc[3][2]+=a.w*b.z; acc[3][3]+=a.w*b.w;
        }
    }
#pragma unroll
    for(int i=0;i<4;i++){
        int rm=m0+ty*4+i;
#pragma unroll
        for(int j=0;j<4;j++){
            int cn=n0+tx*4+j;
            float v=acc[i][j]+bias[cn];
            if(epiMode==1){
                int off=rm&2047;
                if(off<VIS) v+=encoded[(size_t)((rm>>11)*VIS+off)*DIM+cn];
                else        v+=mtok[cn];
            }
            C[(size_t)rm*DIM+cn]=v;
        }
    }
}

// ----- attention: one query per thread, 128 queries per block, online softmax
__global__ void attn_kernel(){
    __shared__ float Ks[128*32];
    __shared__ float Vs[128*32];
    const int tid=threadIdx.x;
    const int b=blockIdx.z, h=blockIdx.y, qt=blockIdx.x;
    const int qrow=b*MSK+qt*128+tid;
    float q[32];
    const float4* qp=(const float4*)(g_Q+(size_t)qrow*DIM+h*DH);
#pragma unroll
    for(int i=0;i<8;i++){
        float4 v=qp[i];
        q[i*4+0]=v.x*0.17677669529663687f; q[i*4+1]=v.y*0.17677669529663687f;
        q[i*4+2]=v.z*0.17677669529663687f; q[i*4+3]=v.w*0.17677669529663687f;
    }
    float m=-1e30f, l=0.f;
    float acc[32];
#pragma unroll
    for(int d=0;d<32;d++) acc[d]=0.f;

    for(int kt=0;kt<4;kt++){
        __syncthreads();
#pragma unroll
        for(int j=0;j<8;j++){
            int pidx=tid+128*j;         // 0..1023 float4 slots
            int r=pidx>>3, c4=pidx&7;
            const float4* kp=(const float4*)(g_K+(size_t)(b*VIS+kt*128+r)*DIM+h*DH);
            const float4* vp=(const float4*)(g_V+(size_t)(b*VIS+kt*128+r)*DIM+h*DH);
            ((float4*)Ks)[r*8+c4]=kp[c4];
            ((float4*)Vs)[r*8+c4]=vp[c4];
        }
        __syncthreads();
        for(int c0=0;c0<128;c0+=8){
            float s[8];
#pragma unroll
            for(int c=0;c<8;c++){
                const float* kr=Ks+(c0+c)*32;
                float sv=0.f;
#pragma unroll
                for(int d=0;d<32;d++) sv+=q[d]*kr[d];
                s[c]=sv;
            }
            float cm=s[0];
#pragma unroll
            for(int c=1;c<8;c++) cm=fmaxf(cm,s[c]);
            float nm=fmaxf(m,cm);
            float rsc=__expf(m-nm);
            l*=rsc;
#pragma unroll
            for(int d=0;d<32;d++) acc[d]*=rsc;
#pragma unroll
            for(int c=0;c<8;c++){
                float p=__expf(s[c]-nm);
                l+=p;
                const float* vr=Vs+(c0+c)*32;
#pragma unroll
                for(int d=0;d<32;d++) acc[d]+=p*vr[d];
            }
            m=nm;
        }
    }
    float inv=1.0f/l;
    float4* op=(float4*)(g_O+(size_t)qrow*DIM+h*DH);
#pragma unroll
    for(int i=0;i<8;i++)
        op[i]=make_float4(acc[i*4+0]*inv,acc[i*4+1]*inv,acc[i*4+2]*inv,acc[i*4+3]*inv);
}

// ----- masked_features = LN(q + attn_out), warp per row -----
__global__ void mf_ln_kernel(const float* __restrict__ gam, const float* __restrict__ bet){
    int w=threadIdx.x>>5, lane=threadIdx.x&31;
    int row=blockIdx.x*8+w;            // 0..NM-1
    int pt=(row/1536)*2048+512+(row%1536);
    float v[8]; float s=0.f, ss=0.f;
#pragma unroll
    for(int j=0;j<8;j++){
        int d=lane+32*j;
        float x=g_X[(size_t)pt*DIM+d]+g_AO[(size_t)row*DIM+d];
        v[j]=x; s+=x; ss+=x*x;
    }
    for(int o=16;o;o>>=1){ s+=__shfl_xor_sync(0xffffffffu,s,o); ss+=__shfl_xor_sync(0xffffffffu,ss,o); }
    float mean=s*(1.0f/256.0f);
    float rstd=rsqrtf(ss*(1.0f/256.0f)-mean*mean+1e-5f);
#pragma unroll
    for(int j=0;j<8;j++){
        int d=lane+32*j;
        g_MF[(size_t)row*DIM+d]=(v[j]-mean)*rstd*gam[d]+bet[d];
    }
}

// ----- transpose decoder weights for coalesced column reads -----
__global__ void prep_wT_kernel(const float* __restrict__ w1, const float* __restrict__ w2){
    int i=blockIdx.x*blockDim.x+threadIdx.x;   // 32768 threads
    if(i<HID*DIM){ int n=i>>8, k=i&255; g_w1T[k*HID+n]=w1[i]; }
    if(i<HID*HID){ int n=i>>7, k=i&127; g_w2T[k*HID+n]=w2[i]; }
}

// ----- fused 3-layer decoder, 4 rows per block, 128 threads -----
__global__ void decoder_kernel(const float* __restrict__ b1, const float* __restrict__ gam,
                               const float* __restrict__ bet, const float* __restrict__ b2,
                               const float* __restrict__ w3, const float* __restrict__ b3,
                               float* __restrict__ out){
    __shared__ float xs[4][DIM];
    __shared__ float g1s[4][HID];
    __shared__ float red[4][8];
    __shared__ float stats[4][2];
    __shared__ float ored[4][4][4];
    const int tid=threadIdx.x, lane=tid&31, wid=tid>>5;
    const int p0=blockIdx.x*4;
#pragma unroll
    for(int r=0;r<4;r++){
        int p=p0+r; int off=p&2047;
        const float* src=(off<VIS) ? (g_X+(size_t)p*DIM)
                                   : (g_MF+(size_t)((p>>11)*MSK+off-VIS)*DIM);
        ((float2*)xs[r])[tid]=((const float2*)src)[tid];
    }
    __syncthreads();
    float h[4]={b1[tid],b1[tid],b1[tid],b1[tid]};
#pragma unroll 4
    for(int k=0;k<DIM;k++){
        float wv=g_w1T[k*HID+tid];
        h[0]+=xs[0][k]*wv; h[1]+=xs[1][k]*wv; h[2]+=xs[2][k]*wv; h[3]+=xs[3][k]*wv;
    }
#pragma unroll
    for(int r=0;r<4;r++){
        float s=h[r], ss=h[r]*h[r];
        for(int o=16;o;o>>=1){ s+=__shfl_xor_sync(0xffffffffu,s,o); ss+=__shfl_xor_sync(0xffffffffu,ss,o); }
        if(lane==0){ red[r][wid]=s; red[r][4+wid]=ss; }
    }
    __syncthreads();
    if(tid<4){
        float s=red[tid][0]+red[tid][1]+red[tid][2]+red[tid][3];
        float ss=red[tid][4]+red[tid][5]+red[tid][6]+red[tid][7];
        float mm=s*(1.0f/128.0f);
        stats[tid][0]=mm;
        stats[tid][1]=rsqrtf(ss*(1.0f/128.0f)-mm*mm+1e-5f);
    }
    __syncthreads();
    float gmv=gam[tid], btv=bet[tid];
#pragma unroll
    for(int r=0;r<4;r++){
        float t=(h[r]-stats[r][0])*stats[r][1]*gmv+btv;
        g1s[r][tid]=gelu(t);
    }
    __syncthreads();
    float h2[4]={b2[tid],b2[tid],b2[tid],b2[tid]};
#pragma unroll 4
    for(int k=0;k<HID;k++){
        float wv=g_w2T[k*HID+tid];
        h2[0]+=g1s[0][k]*wv; h2[1]+=g1s[1][k]*wv; h2[2]+=g1s[2][k]*wv; h2[3]+=g1s[3][k]*wv;
    }
#pragma unroll
    for(int r=0;r<4;r++) h2[r]=gelu(h2[r]);
    float w30=w3[tid], w31=w3[HID+tid], w32=w3[2*HID+tid], w33=w3[3*HID+tid];
#pragma unroll
    for(int r=0;r<4;r++){
        float q0=h2[r]*w30, q1=h2[r]*w31, q2=h2[r]*w32, q3=h2[r]*w33;
        for(int o=16;o;o>>=1){
            q0+=__shfl_xor_sync(0xffffffffu,q0,o);
            q1+=__shfl_xor_sync(0xffffffffu,q1,o);
            q2+=__shfl_xor_sync(0xffffffffu,q2,o);
            q3+=__shfl_xor_sync(0xffffffffu,q3,o);
        }
        if(lane==0){ ored[r][0][wid]=q0; ored[r][1][wid]=q1; ored[r][2][wid]=q2; ored[r][3][wid]=q3; }
    }
    __syncthreads();
    if(tid<16){
        int r=tid>>2, j=tid&3;
        float v=ored[r][j][0]+ored[r][j][1]+ored[r][j][2]+ored[r][j][3]+b3[j];
        out[(size_t)(p0+r)*4+j]=v;
    }
}

// -----------------------------------------------------------------------------
extern "C" void kernel_launch(void* const* d_in, const int* in_sizes, int n_in,
                              void* d_out, int out_size){
    const float* encoded   =(const float*)d_in[0];
    const float* coord     =(const float*)d_in[1];
    const float* mask_token=(const float*)d_in[2];
    const float* pe_w1     =(const float*)d_in[3];
    const float* pe_b1     =(const float*)d_in[4];
    const float* pe_g      =(const float*)d_in[5];
    const float* pe_be     =(const float*)d_in[6];
    const float* pe_w2     =(const float*)d_in[7];
    const float* pe_b2     =(const float*)d_in[8];
    const float* wq        =(const float*)d_in[9];
    const float* bq        =(const float*)d_in[10];
    const float* wk        =(const float*)d_in[11];
    const float* bk        =(const float*)d_in[12];
    const float* wv        =(const float*)d_in[13];
    const float* bv        =(const float*)d_in[14];
    const float* wo        =(const float*)d_in[15];
    const float* bo        =(const float*)d_in[16];
    const float* an_g      =(const float*)d_in[17];
    const float* an_b      =(const float*)d_in[18];
    const float* d_w1      =(const float*)d_in[19];
    const float* d_b1      =(const float*)d_in[20];
    const float* d_g       =(const float*)d_in[21];
    const float* d_be      =(const float*)d_in[22];
    const float* d_w2      =(const float*)d_in[23];
    const float* d_b2      =(const float*)d_in[24];
    const float* d_w3      =(const float*)d_in[25];
    const float* d_b3      =(const float*)d_in[26];
    float* out=(float*)d_out;
    (void)in_sizes; (void)n_in; (void)out_size;

    float *pG=0,*pX=0,*pQ=0,*pK=0,*pV=0,*pO=0,*pAO=0;
    cudaGetSymbolAddress((void**)&pG,  g_gbuf);
    cudaGetSymbolAddress((void**)&pX,  g_X);
    cudaGetSymbolAddress((void**)&pQ,  g_Q);
    cudaGetSymbolAddress((void**)&pK,  g_K);
    cudaGetSymbolAddress((void**)&pV,  g_V);
    cudaGetSymbolAddress((void**)&pO,  g_O);
    cudaGetSymbolAddress((void**)&pAO, g_AO);

    init_mm_kernel<<<1,32>>>();
    mm_kernel<<<64,256>>>(coord);
    pe_stage1_kernel<<<NTOT/8,256>>>(coord, pe_w1, pe_b1, pe_g, pe_be);
    // X = gbuf @ pe_w2^T + pe_b2  (+ encoded / mask_token)
    gemm256_kernel<<<dim3(NTOT/64,4),256>>>(pG, pe_w2, pe_b2, pX, 0, 1, encoded, mask_token);
    // Q/K/V projections (gather masked / visible rows of X)
    gemm256_kernel<<<dim3(NM/64,4),256>>>(pX, wq, bq, pQ, 1, 0, 0, 0);
    gemm256_kernel<<<dim3(NV/64,4),256>>>(pX, wk, bk, pK, 2, 0, 0, 0);
    gemm256_kernel<<<dim3(NV/64,4),256>>>(pX, wv, bv, pV, 2, 0, 0, 0);
    attn_kernel<<<dim3(MSK/128,NHEAD,NB),128>>>();
    gemm256_kernel<<<dim3(NM/64,4),256>>>(pO, wo, bo, pAO, 0, 0, 0, 0);
    mf_ln_kernel<<<NM/8,256>>>(an_g, an_b);
    prep_wT_kernel<<<128,256>>>(d_w1, d_w2);
    decoder_kernel<<<NTOT/4,128>>>(d_b1, d_g, d_be, d_b2, d_w3, d_b3, out);
}

// round 5
// speedup vs baseline: 1.3213x; 1.3213x over previous
#include <cuda_runtime.h>
#include <cuda_bf16.h>
#include <math.h>
#include <stdint.h>

typedef unsigned long long ull;
typedef unsigned int uint;

// Problem constants
#define NTOT  32768
#define DIM   256
#define NB    16
#define VIS   512
#define MSK   1536
#define NV    (NB*VIS)   // 8192
#define NM    (NB*MSK)   // 24576
#define HID   128
#define NHEAD 8
#define DH    32

// ---------------- scratch (device globals; no allocation allowed) -------------
__device__ float g_gbuf[NTOT*DIM];
__device__ float g_X[NTOT*DIM];
__device__ float g_Q[NM*DIM];
__device__ float g_K[NV*DIM];
__device__ float g_V[NV*DIM];
__device__ float g_O[NM*DIM];
__device__ float g_AO[NM*DIM];
__device__ float g_MF[NM*DIM];
__device__ float g_w1T[DIM*HID];
__device__ float g_w2T[HID*HID];
__device__ int   g_mm[6];

// ---------------- helpers ----------------------------------------------------
__device__ __forceinline__ int f2ord(float f){ int i=__float_as_int(f); return i>=0 ? i : (i^0x7fffffff); }
__device__ __forceinline__ float ord2f(int i){ return __int_as_float(i>=0 ? i : (i^0x7fffffff)); }
__device__ __forceinline__ float gelu(float x){ return 0.5f*x*(1.0f+erff(x*0.70710678118654752f)); }

__device__ __forceinline__ ull f2pack(float a, float b){ ull r; asm("mov.b64 %0,{%1,%2};":"=l"(r):"f"(a),"f"(b)); return r; }
__device__ __forceinline__ void f2unpack(ull v, float&a, float&b){ asm("mov.b64 {%0,%1},%2;":"=f"(a),"=f"(b):"l"(v)); }
__device__ __forceinline__ ull ffma2(ull a, ull b, ull c){ ull d; asm("fma.rn.f32x2 %0,%1,%2,%3;":"=l"(d):"l"(a),"l"(b),"l"(c)); return d; }
__device__ __forceinline__ ull fmul2(ull a, ull b){ ull d; asm("mul.rn.f32x2 %0,%1,%2;":"=l"(d):"l"(a),"l"(b)); return d; }

__device__ __forceinline__ uint32_t smem_u32(const void* p){
    uint32_t a; asm("{ .reg .u64 t; cvta.to.shared.u64 t, %1; cvt.u32.u64 %0, t; }" : "=r"(a) : "l"(p)); return a;
}
__device__ __forceinline__ uint pack2bf(float a, float b){
    __nv_bfloat162 h = __floats2bfloat162_rn(a,b);
    return *(uint*)&h;
}
#define LDM4(r0,r1,r2,r3,addr) \
    asm volatile("ldmatrix.sync.aligned.m8n8.x4.shared.b16 {%0,%1,%2,%3}, [%4];" \
        : "=r"(r0),"=r"(r1),"=r"(r2),"=r"(r3) : "r"(addr))
#define MMA16816(d, a, b) \
    asm volatile("mma.sync.aligned.m16n8k16.row.col.f32.bf16.bf16.f32 " \
        "{%0,%1,%2,%3}, {%4,%5,%6,%7}, {%8,%9}, {%0,%1,%2,%3};" \
        : "+f"((d)[0]),"+f"((d)[1]),"+f"((d)[2]),"+f"((d)[3]) \
        : "r"((a)[0]),"r"((a)[1]),"r"((a)[2]),"r"((a)[3]),"r"((b)[0]),"r"((b)[1]))

// ================= min/max ====================================================
__global__ void init_mm_kernel(){
    int t=threadIdx.x;
    if(t<3) g_mm[t]=0x7fffffff;
    else if(t<6) g_mm[t]=0x80000000;
}
__global__ void mm_kernel(const float* __restrict__ coord){
    float mn0=1e30f,mn1=1e30f,mn2=1e30f,mx0=-1e30f,mx1=-1e30f,mx2=-1e30f;
    for(int p=blockIdx.x*blockDim.x+threadIdx.x; p<NTOT; p+=gridDim.x*blockDim.x){
        float a=coord[p*3+0], b=coord[p*3+1], c=coord[p*3+2];
        mn0=fminf(mn0,a); mx0=fmaxf(mx0,a);
        mn1=fminf(mn1,b); mx1=fmaxf(mx1,b);
        mn2=fminf(mn2,c); mx2=fmaxf(mx2,c);
    }
    for(int o=16;o;o>>=1){
        mn0=fminf(mn0,__shfl_xor_sync(0xffffffffu,mn0,o));
        mn1=fminf(mn1,__shfl_xor_sync(0xffffffffu,mn1,o));
        mn2=fminf(mn2,__shfl_xor_sync(0xffffffffu,mn2,o));
        mx0=fmaxf(mx0,__shfl_xor_sync(0xffffffffu,mx0,o));
        mx1=fmaxf(mx1,__shfl_xor_sync(0xffffffffu,mx1,o));
        mx2=fmaxf(mx2,__shfl_xor_sync(0xffffffffu,mx2,o));
    }
    if((threadIdx.x&31)==0){
        atomicMin(&g_mm[0],f2ord(mn0)); atomicMin(&g_mm[1],f2ord(mn1)); atomicMin(&g_mm[2],f2ord(mn2));
        atomicMax(&g_mm[3],f2ord(mx0)); atomicMax(&g_mm[4],f2ord(mx1)); atomicMax(&g_mm[5],f2ord(mx2));
    }
}

// ================= pos-embed stage 1 =========================================
__global__ void pe_stage1_kernel(const float* __restrict__ coord,
                                 const float* __restrict__ w1, const float* __restrict__ b1,
                                 const float* __restrict__ gam, const float* __restrict__ bet){
    int w=threadIdx.x>>5, lane=threadIdx.x&31;
    int p=blockIdx.x*8+w;
    float lo0=ord2f(g_mm[0]), lo1=ord2f(g_mm[1]), lo2=ord2f(g_mm[2]);
    float s0=fmaxf(ord2f(g_mm[3])-lo0,1.0f);
    float s1=fmaxf(ord2f(g_mm[4])-lo1,1.0f);
    float s2=fmaxf(ord2f(g_mm[5])-lo2,1.0f);
    float c0=(coord[p*3+0]-lo0)/s0;
    float c1=(coord[p*3+1]-lo1)/s1;
    float c2=(coord[p*3+2]-lo2)/s2;
    float v[8]; float s=0.f, ss=0.f;
#pragma unroll
    for(int j=0;j<8;j++){
        int d=lane+32*j;
        float h=c0*w1[d*3+0]+c1*w1[d*3+1]+c2*w1[d*3+2]+b1[d];
        v[j]=h; s+=h; ss+=h*h;
    }
    for(int o=16;o;o>>=1){ s+=__shfl_xor_sync(0xffffffffu,s,o); ss+=__shfl_xor_sync(0xffffffffu,ss,o); }
    float mean=s*(1.0f/256.0f);
    float rstd=rsqrtf(ss*(1.0f/256.0f)-mean*mean+1e-5f);
#pragma unroll
    for(int j=0;j<8;j++){
        int d=lane+32*j;
        float t=(v[j]-mean)*rstd*gam[d]+bet[d];
        g_gbuf[p*DIM+d]=gelu(t);
    }
}

// ================= bf16x3 emulated-fp32 mma GEMM =============================
// C[m, n0:n0+128] = sum_k A[map(m),k]*W[n,k] + bias[n] (+epi).  K=256.
// CTA: 128x128 tile, 256 thr (8 warps, each 64x32). K chunks of 32 in smem,
// stride 40 bf16 (80B: 16B-aligned rows, conflict-free ldmatrix).
#define KSTR 40
__global__ void __launch_bounds__(256) mma_gemm_kernel(
        const float* __restrict__ A, const float* __restrict__ W,
        const float* __restrict__ bias, float* __restrict__ C,
        int gatherMode, int epiMode,
        const float* __restrict__ encoded, const float* __restrict__ mtok){
    __shared__ __align__(16) unsigned short Ahi[128*KSTR], Alo[128*KSTR];
    __shared__ __align__(16) unsigned short Bhi[128*KSTR], Blo[128*KSTR];
    const int tid=threadIdx.x, lane=tid&31, wid=tid>>5;
    const int m0=blockIdx.x*128, n0=blockIdx.y*128;
    const int wm=(wid>>2)*64, wn=(wid&3)*32;

    // staging: each thread owns one row-half (16 floats) of A and B per chunk
    const int lrow=tid>>1, hc=(tid&1)*16;
    int cm=m0+lrow, arow;
    if(gatherMode==1)      arow=(cm/1536)*2048+512+(cm%1536);
    else if(gatherMode==2) arow=(cm>>9)*2048+(cm&511);
    else                   arow=cm;
    const float* ag=A+(size_t)arow*DIM+hc;
    const float* bg=W+(size_t)(n0+lrow)*DIM+hc;
    const int sidx=lrow*KSTR+hc;

    uint32_t aHi=smem_u32(Ahi), aLo=smem_u32(Alo), bHi=smem_u32(Bhi), bLo=smem_u32(Blo);
    // per-lane ldmatrix row/col bases
    const int a_r=wm+(lane&7)+((lane>>3)&1)*8;   // + mt*16
    const int a_c=(lane>>4)*8;                    // + ks*16
    const int b_r=wn+(lane&7)+(lane>>4)*8;        // + bt*16
    const int b_c=((lane>>3)&1)*8;                // + ks*16

    float acc[4][4][4];
#pragma unroll
    for(int i=0;i<4;i++)
#pragma unroll
        for(int j=0;j<4;j++)
#pragma unroll
            for(int k=0;k<4;k++) acc[i][j][k]=0.f;

    float4 pa[4], pb[4];
    {
        const float4* pA=(const float4*)ag; const float4* pB=(const float4*)bg;
        pa[0]=pA[0]; pa[1]=pA[1]; pa[2]=pA[2]; pa[3]=pA[3];
        pb[0]=pB[0]; pb[1]=pB[1]; pb[2]=pB[2]; pb[3]=pB[3];
    }

    for(int c=0;c<8;c++){
        __syncthreads();
        // convert + store staged chunk
        {
            const float* xa=(const float*)pa;
            const float* xb=(const float*)pb;
            uint ha[8],la[8],hb[8],lb[8];
#pragma unroll
            for(int j=0;j<8;j++){
                float x0=xa[2*j], x1=xa[2*j+1];
                __nv_bfloat16 h0=__float2bfloat16_rn(x0), h1=__float2bfloat16_rn(x1);
                ha[j]=pack2bf(x0,x1);
                la[j]=pack2bf(x0-__bfloat162float(h0), x1-__bfloat162float(h1));
                float y0=xb[2*j], y1=xb[2*j+1];
                __nv_bfloat16 g0=__float2bfloat16_rn(y0), g1=__float2bfloat16_rn(y1);
                hb[j]=pack2bf(y0,y1);
                lb[j]=pack2bf(y0-__bfloat162float(g0), y1-__bfloat162float(g1));
            }
            *(uint4*)&Ahi[sidx  ]=make_uint4(ha[0],ha[1],ha[2],ha[3]);
            *(uint4*)&Ahi[sidx+8]=make_uint4(ha[4],ha[5],ha[6],ha[7]);
            *(uint4*)&Alo[sidx  ]=make_uint4(la[0],la[1],la[2],la[3]);
            *(uint4*)&Alo[sidx+8]=make_uint4(la[4],la[5],la[6],la[7]);
            *(uint4*)&Bhi[sidx  ]=make_uint4(hb[0],hb[1],hb[2],hb[3]);
            *(uint4*)&Bhi[sidx+8]=make_uint4(hb[4],hb[5],hb[6],hb[7]);
            *(uint4*)&Blo[sidx  ]=make_uint4(lb[0],lb[1],lb[2],lb[3]);
            *(uint4*)&Blo[sidx+8]=make_uint4(lb[4],lb[5],lb[6],lb[7]);
        }
        __syncthreads();
        if(c<7){
            const float4* pA=(const float4*)(ag+(c+1)*32);
            const float4* pB=(const float4*)(bg+(c+1)*32);
            pa[0]=pA[0]; pa[1]=pA[1]; pa[2]=pA[2]; pa[3]=pA[3];
            pb[0]=pB[0]; pb[1]=pB[1]; pb[2]=pB[2]; pb[3]=pB[3];
        }
#pragma unroll
        for(int ks=0;ks<2;ks++){
            uint ah[4][4], al[4][4], bh[4][2], bl[4][2];
#pragma unroll
            for(int mt=0;mt<4;mt++){
                uint32_t off=(uint32_t)(((a_r+mt*16)*KSTR + a_c + ks*16)*2);
                LDM4(ah[mt][0],ah[mt][1],ah[mt][2],ah[mt][3], aHi+off);
                LDM4(al[mt][0],al[mt][1],al[mt][2],al[mt][3], aLo+off);
            }
#pragma unroll
            for(int bt=0;bt<2;bt++){
                uint32_t off=(uint32_t)(((b_r+bt*16)*KSTR + b_c + ks*16)*2);
                uint r0,r1,r2,r3;
                LDM4(r0,r1,r2,r3, bHi+off);
                bh[2*bt][0]=r0; bh[2*bt][1]=r1; bh[2*bt+1][0]=r2; bh[2*bt+1][1]=r3;
                LDM4(r0,r1,r2,r3, bLo+off);
                bl[2*bt][0]=r0; bl[2*bt][1]=r1; bl[2*bt+1][0]=r2; bl[2*bt+1][1]=r3;
            }
#pragma unroll
            for(int mt=0;mt<4;mt++)
#pragma unroll
                for(int nt=0;nt<4;nt++){
                    MMA16816(acc[mt][nt], ah[mt], bh[nt]);
                    MMA16816(acc[mt][nt], ah[mt], bl[nt]);
                    MMA16816(acc[mt][nt], al[mt], bh[nt]);
                }
        }
    }

    // epilogue
#pragma unroll
    for(int mt=0;mt<4;mt++){
        int r0=m0+wm+mt*16+(lane>>2);
        int r1=r0+8;
        const float *ap0=0,*ap1=0;
        if(epiMode==1){
            int off0=r0&2047; ap0=(off0<VIS)? encoded+(size_t)((r0>>11)*VIS+off0)*DIM : mtok;
            int off1=r1&2047; ap1=(off1<VIS)? encoded+(size_t)((r1>>11)*VIS+off1)*DIM : mtok;
        }
#pragma unroll
        for(int nt=0;nt<4;nt++){
            int cc=n0+wn+nt*8+(lane&3)*2;
            float b0v=bias[cc], b1v=bias[cc+1];
            float v00=acc[mt][nt][0]+b0v, v01=acc[mt][nt][1]+b1v;
            float v10=acc[mt][nt][2]+b0v, v11=acc[mt][nt][3]+b1v;
            if(epiMode==1){ v00+=ap0[cc]; v01+=ap0[cc+1]; v10+=ap1[cc]; v11+=ap1[cc+1]; }
            *(float2*)(C+(size_t)r0*DIM+cc)=make_float2(v00,v01);
            *(float2*)(C+(size_t)r1*DIM+cc)=make_float2(v10,v11);
        }
    }
}

// ================= attention (f32x2 packed FMA) ===============================
__global__ void attn_kernel(){
    __shared__ float Ks[128*32];
    __shared__ float Vs[128*32];
    const int tid=threadIdx.x;
    const int b=blockIdx.z, h=blockIdx.y, qt=blockIdx.x;
    const int qrow=b*MSK+qt*128+tid;
    ull q2[16];
    const float4* qp=(const float4*)(g_Q+(size_t)qrow*DIM+h*DH);
#pragma unroll
    for(int i=0;i<8;i++){
        float4 v=qp[i];
        q2[i*2+0]=f2pack(v.x*0.17677669529663687f, v.y*0.17677669529663687f);
        q2[i*2+1]=f2pack(v.z*0.17677669529663687f, v.w*0.17677669529663687f);
    }
    float m=-1e30f, l=0.f;
    ull acc2[16];
#pragma unroll
    for(int i=0;i<16;i++) acc2[i]=0ull;

    for(int kt=0;kt<4;kt++){
        __syncthreads();
#pragma unroll
        for(int j=0;j<8;j++){
            int pidx=tid+128*j;
            int r=pidx>>3, c4=pidx&7;
            const float4* kp=(const float4*)(g_K+(size_t)(b*VIS+kt*128+r)*DIM+h*DH);
            const float4* vp=(const float4*)(g_V+(size_t)(b*VIS+kt*128+r)*DIM+h*DH);
            ((float4*)Ks)[r*8+c4]=kp[c4];
            ((float4*)Vs)[r*8+c4]=vp[c4];
        }
        __syncthreads();
        for(int c0=0;c0<128;c0+=8){
            float s[8];
#pragma unroll
            for(int c=0;c<8;c++){
                const ull* kr=(const ull*)(Ks+(c0+c)*32);
                ull sa=0ull;
#pragma unroll
                for(int i=0;i<16;i++) sa=ffma2(q2[i],kr[i],sa);
                float lo,hi; f2unpack(sa,lo,hi);
                s[c]=lo+hi;
            }
            float cm=s[0];
#pragma unroll
            for(int c=1;c<8;c++) cm=fmaxf(cm,s[c]);
            float nm=fmaxf(m,cm);
            float rsc=__expf(m-nm);
            l*=rsc;
            ull rr=f2pack(rsc,rsc);
#pragma unroll
            for(int i=0;i<16;i++) acc2[i]=fmul2(acc2[i],rr);
#pragma unroll
            for(int c=0;c<8;c++){
                float p=__expf(s[c]-nm);
                l+=p;
                ull pp=f2pack(p,p);
                const ull* vr=(const ull*)(Vs+(c0+c)*32);
#pragma unroll
                for(int i=0;i<16;i++) acc2[i]=ffma2(pp,vr[i],acc2[i]);
            }
            m=nm;
        }
    }
    float inv=1.0f/l;
    float* op=g_O+(size_t)qrow*DIM+h*DH;
#pragma unroll
    for(int i=0;i<16;i++){
        float lo,hi; f2unpack(acc2[i],lo,hi);
        op[i*2+0]=lo*inv; op[i*2+1]=hi*inv;
    }
}

// ================= residual LN ================================================
__global__ void mf_ln_kernel(const float* __restrict__ gam, const float* __restrict__ bet){
    int w=threadIdx.x>>5, lane=threadIdx.x&31;
    int row=blockIdx.x*8+w;
    int pt=(row/1536)*2048+512+(row%1536);
    float v[8]; float s=0.f, ss=0.f;
#pragma unroll
    for(int j=0;j<8;j++){
        int d=lane+32*j;
        float x=g_X[(size_t)pt*DIM+d]+g_AO[(size_t)row*DIM+d];
        v[j]=x; s+=x; ss+=x*x;
    }
    for(int o=16;o;o>>=1){ s+=__shfl_xor_sync(0xffffffffu,s,o); ss+=__shfl_xor_sync(0xffffffffu,ss,o); }
    float mean=s*(1.0f/256.0f);
    float rstd=rsqrtf(ss*(1.0f/256.0f)-mean*mean+1e-5f);
#pragma unroll
    for(int j=0;j<8;j++){
        int d=lane+32*j;
        g_MF[(size_t)row*DIM+d]=(v[j]-mean)*rstd*gam[d]+bet[d];
    }
}

// ================= decoder ====================================================
__global__ void prep_wT_kernel(const float* __restrict__ w1, const float* __restrict__ w2){
    int i=blockIdx.x*blockDim.x+threadIdx.x;
    if(i<HID*DIM){ int n=i>>8, k=i&255; g_w1T[k*HID+n]=w1[i]; }
    if(i<HID*HID){ int n=i>>7, k=i&127; g_w2T[k*HID+n]=w2[i]; }
}

__global__ void decoder_kernel(const float* __restrict__ b1, const float* __restrict__ gam,
                               const float* __restrict__ bet, const float* __restrict__ b2,
                               const float* __restrict__ w3, const float* __restrict__ b3,
                               float* __restrict__ out){
    __shared__ float xs[4][DIM];
    __shared__ float g1s[4][HID];
    __shared__ float red[4][8];
    __shared__ float stats[4][2];
    __shared__ float ored[4][4][4];
    const int tid=threadIdx.x, lane=tid&31, wid=tid>>5;
    const int p0=blockIdx.x*4;
#pragma unroll
    for(int r=0;r<4;r++){
        int p=p0+r; int off=p&2047;
        const float* src=(off<VIS) ? (g_X+(size_t)p*DIM)
                                   : (g_MF+(size_t)((p>>11)*MSK+off-VIS)*DIM);
        ((float2*)xs[r])[tid]=((const float2*)src)[tid];
    }
    __syncthreads();
    float h[4]={b1[tid],b1[tid],b1[tid],b1[tid]};
#pragma unroll 4
    for(int k=0;k<DIM;k++){
        float wv=g_w1T[k*HID+tid];
        h[0]+=xs[0][k]*wv; h[1]+=xs[1][k]*wv; h[2]+=xs[2][k]*wv; h[3]+=xs[3][k]*wv;
    }
#pragma unroll
    for(int r=0;r<4;r++){
        float s=h[r], ss=h[r]*h[r];
        for(int o=16;o;o>>=1){ s+=__shfl_xor_sync(0xffffffffu,s,o); ss+=__shfl_xor_sync(0xffffffffu,ss,o); }
        if(lane==0){ red[r][wid]=s; red[r][4+wid]=ss; }
    }
    __syncthreads();
    if(tid<4){
        float s=red[tid][0]+red[tid][1]+red[tid][2]+red[tid][3];
        float ss=red[tid][4]+red[tid][5]+red[tid][6]+red[tid][7];
        float mm=s*(1.0f/128.0f);
        stats[tid][0]=mm;
        stats[tid][1]=rsqrtf(ss*(1.0f/128.0f)-mm*mm+1e-5f);
    }
    __syncthreads();
    float gmv=gam[tid], btv=bet[tid];
#pragma unroll
    for(int r=0;r<4;r++){
        float t=(h[r]-stats[r][0])*stats[r][1]*gmv+btv;
        g1s[r][tid]=gelu(t);
    }
    __syncthreads();
    float h2[4]={b2[tid],b2[tid],b2[tid],b2[tid]};
#pragma unroll 4
    for(int k=0;k<HID;k++){
        float wv=g_w2T[k*HID+tid];
        h2[0]+=g1s[0][k]*wv; h2[1]+=g1s[1][k]*wv; h2[2]+=g1s[2][k]*wv; h2[3]+=g1s[3][k]*wv;
    }
#pragma unroll
    for(int r=0;r<4;r++) h2[r]=gelu(h2[r]);
    float w30=w3[tid], w31=w3[HID+tid], w32=w3[2*HID+tid], w33=w3[3*HID+tid];
#pragma unroll
    for(int r=0;r<4;r++){
        float q0=h2[r]*w30, q1=h2[r]*w31, q2=h2[r]*w32, q3=h2[r]*w33;
        for(int o=16;o;o>>=1){
            q0+=__shfl_xor_sync(0xffffffffu,q0,o);
            q1+=__shfl_xor_sync(0xffffffffu,q1,o);
            q2+=__shfl_xor_sync(0xffffffffu,q2,o);
            q3+=__shfl_xor_sync(0xffffffffu,q3,o);
        }
        if(lane==0){ ored[r][0][wid]=q0; ored[r][1][wid]=q1; ored[r][2][wid]=q2; ored[r][3][wid]=q3; }
    }
    __syncthreads();
    if(tid<16){
        int r=tid>>2, j=tid&3;
        float v=ored[r][j][0]+ored[r][j][1]+ored[r][j][2]+ored[r][j][3]+b3[j];
        out[(size_t)(p0+r)*4+j]=v;
    }
}

// -----------------------------------------------------------------------------
extern "C" void kernel_launch(void* const* d_in, const int* in_sizes, int n_in,
                              void* d_out, int out_size){
    const float* encoded   =(const float*)d_in[0];
    const float* coord     =(const float*)d_in[1];
    const float* mask_token=(const float*)d_in[2];
    const float* pe_w1     =(const float*)d_in[3];
    const float* pe_b1     =(const float*)d_in[4];
    const float* pe_g      =(const float*)d_in[5];
    const float* pe_be     =(const float*)d_in[6];
    const float* pe_w2     =(const float*)d_in[7];
    const float* pe_b2     =(const float*)d_in[8];
    const float* wq        =(const float*)d_in[9];
    const float* bq        =(const float*)d_in[10];
    const float* wk        =(const float*)d_in[11];
    const float* bk        =(const float*)d_in[12];
    const float* wv        =(const float*)d_in[13];
    const float* bv        =(const float*)d_in[14];
    const float* wo        =(const float*)d_in[15];
    const float* bo        =(const float*)d_in[16];
    const float* an_g      =(const float*)d_in[17];
    const float* an_b      =(const float*)d_in[18];
    const float* d_w1      =(const float*)d_in[19];
    const float* d_b1      =(const float*)d_in[20];
    const float* d_g       =(const float*)d_in[21];
    const float* d_be      =(const float*)d_in[22];
    const float* d_w2      =(const float*)d_in[23];
    const float* d_b2      =(const float*)d_in[24];
    const float* d_w3      =(const float*)d_in[25];
    const float* d_b3      =(const float*)d_in[26];
    float* out=(float*)d_out;
    (void)in_sizes; (void)n_in; (void)out_size;

    float *pG=0,*pX=0,*pQ=0,*pK=0,*pV=0,*pO=0,*pAO=0;
    cudaGetSymbolAddress((void**)&pG,  g_gbuf);
    cudaGetSymbolAddress((void**)&pX,  g_X);
    cudaGetSymbolAddress((void**)&pQ,  g_Q);
    cudaGetSymbolAddress((void**)&pK,  g_K);
    cudaGetSymbolAddress((void**)&pV,  g_V);
    cudaGetSymbolAddress((void**)&pO,  g_O);
    cudaGetSymbolAddress((void**)&pAO, g_AO);

    init_mm_kernel<<<1,32>>>();
    mm_kernel<<<64,256>>>(coord);
    pe_stage1_kernel<<<NTOT/8,256>>>(coord, pe_w1, pe_b1, pe_g, pe_be);
    mma_gemm_kernel<<<dim3(NTOT/128,2),256>>>(pG, pe_w2, pe_b2, pX, 0, 1, encoded, mask_token);
    mma_gemm_kernel<<<dim3(NM/128,2),256>>>(pX, wq, bq, pQ, 1, 0, 0, 0);
    mma_gemm_kernel<<<dim3(NV/128,2),256>>>(pX, wk, bk, pK, 2, 0, 0, 0);
    mma_gemm_kernel<<<dim3(NV/128,2),256>>>(pX, wv, bv, pV, 2, 0, 0, 0);
    attn_kernel<<<dim3(MSK/128,NHEAD,NB),128>>>();
    mma_gemm_kernel<<<dim3(NM/128,2),256>>>(pO, wo, bo, pAO, 0, 0, 0, 0);
    mf_ln_kernel<<<NM/8,256>>>(an_g, an_b);
    prep_wT_kernel<<<128,256>>>(d_w1, d_w2);
    decoder_kernel<<<NTOT/4,128>>>(d_b1, d_g, d_be, d_b2, d_w3, d_b3, out);
}